// round 1
// baseline (speedup 1.0000x reference)
#include <cuda_runtime.h>
#include <cuda_bf16.h>
#include <cstddef>

// Problem constants
#define TT 4
#define BB 16
#define CIN 3
#define HIMG 64
#define WIMG 64
#define NN 6
#define COUT 128
#define HP 32
#define WP 32

// Persistent state (device globals; zeroed at start of every launch)
__device__ float g_v0[BB * COUT * HIMG * WIMG];          // 8.39M
__device__ float g_vn[5 * BB * COUT * HP * WP];          // 10.49M
__device__ float g_traces[BB * NN * COUT];
__device__ float g_out0[BB * COUT * HP * WP];
__device__ float g_mean0[BB * COUT];
__device__ float g_feat0[BB * COUT];
__device__ float g_msp[5 * BB * COUT];
__device__ float g_c[BB * NN];

__device__ __forceinline__ float sigf(float x) { return 1.f / (1.f + expf(-x)); }

// ---------------------------------------------------------------------------
// K0: zero state
// ---------------------------------------------------------------------------
__global__ void k0_zero() {
    const size_t n0 = (size_t)BB * COUT * HIMG * WIMG;
    const size_t n1 = (size_t)5 * BB * COUT * HP * WP;
    const size_t n2 = (size_t)BB * NN * COUT;
    const size_t tot = n0 + n1 + n2;
    for (size_t i = (size_t)blockIdx.x * blockDim.x + threadIdx.x; i < tot;
         i += (size_t)gridDim.x * blockDim.x) {
        if (i < n0) g_v0[i] = 0.f;
        else if (i < n0 + n1) g_vn[i - n0] = 0.f;
        else g_traces[i - n0 - n1] = 0.f;
    }
}

// ---------------------------------------------------------------------------
// K1: conv0(3->128, 3x3, SAME) + BN + PLIF + spike + 2x2 avgpool
//     writes out0, v0 state, node-0 output term, per-(b,c) spatial mean.
// grid (B, COUT), 256 threads, dynamic smem = 3*66*66 floats
// ---------------------------------------------------------------------------
__global__ void k1_conv0(const float* __restrict__ x, const float* __restrict__ w0,
                         const float* __restrict__ bg, const float* __restrict__ bb,
                         const float* __restrict__ bm, const float* __restrict__ bv,
                         const float* __restrict__ plw, const float* __restrict__ outw,
                         float* __restrict__ dout, int t) {
    extern __shared__ float tile[];   // [3][66][66]
    __shared__ float ws[27];
    __shared__ float red[256];
    int b = blockIdx.x, c = blockIdx.y, tid = threadIdx.x;

    const float* xb = x + (((size_t)t * BB + b) * CIN) * (HIMG * WIMG);
    for (int idx = tid; idx < 3 * 66 * 66; idx += 256) {
        int ic = idx / 4356, rem = idx % 4356;
        int r = rem / 66, cc = rem % 66;
        int y = r - 1, xx = cc - 1;
        float v = 0.f;
        if ((unsigned)y < 64u && (unsigned)xx < 64u) v = xb[ic * 4096 + y * 64 + xx];
        tile[idx] = v;
    }
    if (tid < 27) ws[tid] = w0[c * 27 + tid];
    __syncthreads();

    float scale = bg[c] / sqrtf(bv[c] + 1e-5f);
    float shift = bb[c] - bm[c] * scale;
    float sg = sigf(plw[0]);
    float wsig0 = sigf(outw[0]);

    float* v0p = g_v0 + ((size_t)b * COUT + c) * (HIMG * WIMG);
    float* o0p = g_out0 + ((size_t)b * COUT + c) * (HP * WP);
    float* dop = dout + ((((size_t)t * BB + b) * COUT + c)) * (HP * WP);

    float lsum = 0.f;
    for (int k = 0; k < 4; k++) {
        int q = tid + k * 256;
        int ph = q >> 5, pw = q & 31;
        float psum = 0.f;
        #pragma unroll
        for (int dy = 0; dy < 2; dy++) {
            #pragma unroll
            for (int dx = 0; dx < 2; dx++) {
                int yy = 2 * ph + dy, xx = 2 * pw + dx;
                float acc = 0.f;
                #pragma unroll
                for (int ic = 0; ic < 3; ic++) {
                    const float* tp = tile + ic * 4356 + yy * 66 + xx;
                    const float* wp = ws + ic * 9;
                    #pragma unroll
                    for (int ky = 0; ky < 3; ky++)
                        #pragma unroll
                        for (int kx = 0; kx < 3; kx++)
                            acc += tp[ky * 66 + kx] * wp[ky * 3 + kx];
                }
                float bnv = acc * scale + shift;
                float vold = v0p[yy * 64 + xx];
                float v = vold + (bnv - vold) * sg;
                float sp = (v >= 1.f) ? 1.f : 0.f;
                v0p[yy * 64 + xx] = (v >= 1.f) ? 0.f : v;
                psum += sp;
            }
        }
        float o = psum * 0.25f;
        o0p[q] = o;
        dop[q] = wsig0 * o;     // node-0 output term ('=' clears poison)
        lsum += o;
    }
    red[tid] = lsum;
    __syncthreads();
    for (int off = 128; off; off >>= 1) {
        if (tid < off) red[tid] += red[tid + off];
        __syncthreads();
    }
    if (tid == 0) g_mean0[b * COUT + c] = red[0] * (1.f / 1024.f);
}

// ---------------------------------------------------------------------------
// K2: per-batch tiny graph work: feat0, trace0 update, GAT adjacency,
//     softmax(T=0.01), top-3 prune, diffusion op, c[b,i] = (op@op)[:,i,0]
// grid (B), 128 threads
// ---------------------------------------------------------------------------
__global__ void k2_graph(const float* __restrict__ ftw, const float* __restrict__ ftb,
                         const float* __restrict__ gatW, const float* __restrict__ gata) {
    int b = blockIdx.x, tid = threadIdx.x;
    __shared__ float tr[NN * COUT];
    __shared__ float m0[COUT];
    __shared__ float hp[NN * COUT];
    __shared__ float e1[NN * 4], e2[NN * 4];
    __shared__ float attn[36], Sm[36], adj[36], opm[36], dis[NN];

    m0[tid] = g_mean0[b * COUT + tid];
    for (int n = 0; n < NN; n++) tr[n * COUT + tid] = g_traces[((size_t)b * NN + n) * COUT + tid];
    __syncthreads();

    // feat0 = relu(mean0 @ ft_w^T + ft_b)
    float f = ftb[tid];
    for (int d = 0; d < COUT; d++) f += m0[d] * ftw[tid * COUT + d];
    f = fmaxf(f, 0.f);
    g_feat0[b * COUT + tid] = f;
    float t0 = 0.6f * tr[tid] + 0.4f * f;
    tr[tid] = t0;
    g_traces[(size_t)b * NN * COUT + tid] = t0;
    __syncthreads();

    // hp = traces @ gat_W^T
    for (int n = 0; n < NN; n++) {
        float s = 0.f;
        for (int k = 0; k < COUT; k++) s += tr[n * COUT + k] * gatW[tid * COUT + k];
        hp[n * COUT + tid] = s;
    }
    __syncthreads();

    if (tid < NN * 4) {
        int n = tid >> 2, h = tid & 3;
        float s1 = 0.f, s2 = 0.f;
        for (int d = 0; d < 32; d++) {
            float hv = hp[n * COUT + h * 32 + d];
            s1 += hv * gata[h * 64 + d];
            s2 += hv * gata[h * 64 + 32 + d];
        }
        e1[tid] = s1;
        e2[tid] = s2;
    }
    __syncthreads();

    if (tid < 36) {
        int i = tid / 6, j = tid % 6;
        float s = 0.f;
        for (int h = 0; h < 4; h++) {
            float x1 = e1[i * 4 + h] + e2[j * 4 + h];
            float x2 = e1[j * 4 + h] + e2[i * 4 + h];
            x1 = x1 > 0.f ? x1 : 0.2f * x1;
            x2 = x2 > 0.f ? x2 : 0.2f * x2;
            s += 0.5f * (x1 + x2);
        }
        attn[tid] = s * 0.25f;
    }
    __syncthreads();

    if (tid < NN) {  // softmax over row, temp 0.01
        int i = tid;
        float mx = -1e30f;
        for (int j = 0; j < 6; j++) mx = fmaxf(mx, attn[i * 6 + j] * 100.f);
        float ex[6], sum = 0.f;
        for (int j = 0; j < 6; j++) { ex[j] = expf(attn[i * 6 + j] * 100.f - mx); sum += ex[j]; }
        for (int j = 0; j < 6; j++) Sm[i * 6 + j] = ex[j] / sum;
    }
    __syncthreads();

    if (tid < NN) {  // prune: keep >= 3rd largest
        int i = tid;
        float a[6];
        for (int j = 0; j < 6; j++) a[j] = Sm[i * 6 + j];
        float kth = 0.f;
        for (int r = 0; r < 3; r++) {
            int bi = 0; float bvv = -1e30f;
            for (int j = 0; j < 6; j++) if (a[j] > bvv) { bvv = a[j]; bi = j; }
            kth = bvv; a[bi] = -1e30f;
        }
        for (int j = 0; j < 6; j++) Sm[i * 6 + j] = (Sm[i * 6 + j] >= kth) ? Sm[i * 6 + j] : 0.f;
    }
    __syncthreads();

    if (tid < 36) { int i = tid / 6, j = tid % 6; adj[tid] = 0.5f * (Sm[i * 6 + j] + Sm[j * 6 + i]); }
    __syncthreads();
    if (tid < NN) {
        float s = 0.f;
        for (int j = 0; j < 6; j++) s += adj[tid * 6 + j];
        dis[tid] = 1.f / sqrtf(s + 1e-6f);
    }
    __syncthreads();
    if (tid < 36) { int i = tid / 6, j = tid % 6; opm[tid] = dis[i] * adj[tid] * dis[j]; }
    __syncthreads();
    if (tid < NN) {
        float s = 0.f;
        for (int j = 0; j < 6; j++) s += opm[tid * 6 + j] * opm[j * 6 + 0];
        g_c[b * NN + tid] = s;
    }
}

// ---------------------------------------------------------------------------
// K3: batched node conv: 5 convs (128->128, 3x3, SAME on 32x32) over out0,
//     with the diffusion scalar c[b,i] folded into the BN affine; then
//     PLIF + spike + v_nodes update + output accumulation + per-node spike mean.
// grid (B, COUT/2); 256 threads: half-block per c_out, 8-px strip per thread.
// ---------------------------------------------------------------------------
__global__ void __launch_bounds__(256) k3_nodeconv(
    const float* __restrict__ convw, const float* __restrict__ bg,
    const float* __restrict__ bb, const float* __restrict__ bm,
    const float* __restrict__ bv, const float* __restrict__ plw,
    const float* __restrict__ outw, float* __restrict__ dout, int t) {
    __shared__ float in_s[8 * 1156];   // 8 ic x 34x34 (halo'd)
    __shared__ float w_s[720];         // 2 co x 5 nodes x 8 ic x 9
    int b = blockIdx.x, cp = blockIdx.y, tid = threadIdx.x;
    int half = tid >> 7, t2 = tid & 127;
    int co = cp * 2 + half;
    int row = t2 >> 2, x0 = (t2 & 3) * 8;

    float acc[5][8];
    #pragma unroll
    for (int i = 0; i < 5; i++)
        #pragma unroll
        for (int p = 0; p < 8; p++) acc[i][p] = 0.f;

    const float* o0b = g_out0 + (size_t)b * COUT * (HP * WP);

    for (int kc = 0; kc < 16; kc++) {
        __syncthreads();
        for (int idx = tid; idx < 9248; idx += 256) {
            int ic = idx / 1156, rem = idx % 1156;
            int r = rem / 34, cc = rem % 34;
            int y = r - 1, xx = cc - 1;
            float v = 0.f;
            if ((unsigned)y < 32u && (unsigned)xx < 32u)
                v = o0b[(size_t)(kc * 8 + ic) * 1024 + y * 32 + xx];
            in_s[idx] = v;
        }
        for (int idx = tid; idx < 720; idx += 256) {
            int h2 = idx / 360, r = idx % 360;
            int i = r / 72, r2 = r % 72, ic = r2 / 9, k = r2 % 9;
            int col = cp * 2 + h2;
            w_s[idx] = convw[(((size_t)i * COUT + col) * COUT + kc * 8 + ic) * 9 + k];
        }
        __syncthreads();
        #pragma unroll
        for (int ic = 0; ic < 8; ic++) {
            const float* ip = in_s + ic * 1156;
            const float* wp = w_s + half * 360 + ic * 9;
            #pragma unroll
            for (int ky = 0; ky < 3; ky++) {
                float v[10];
                const float* rp = ip + (row + ky) * 34 + x0;
                #pragma unroll
                for (int j = 0; j < 10; j++) v[j] = rp[j];
                #pragma unroll
                for (int i = 0; i < 5; i++) {
                    float w0 = wp[i * 72 + ky * 3 + 0];
                    float w1 = wp[i * 72 + ky * 3 + 1];
                    float w2 = wp[i * 72 + ky * 3 + 2];
                    #pragma unroll
                    for (int p = 0; p < 8; p++)
                        acc[i][p] += v[p] * w0 + v[p + 1] * w1 + v[p + 2] * w2;
                }
            }
        }
    }

    // Epilogue: scale by c, BN, PLIF, spike, state write, output accumulate
    float outacc[8];
    #pragma unroll
    for (int p = 0; p < 8; p++) outacc[p] = 0.f;
    float spsum[5];
    int pxbase = row * 32 + x0;

    #pragma unroll
    for (int i = 0; i < 5; i++) {
        float ci = g_c[b * NN + i + 1];
        float sc = bg[i * COUT + co] / sqrtf(bv[i * COUT + co] + 1e-5f);
        float sh = bb[i * COUT + co] - bm[i * COUT + co] * sc;
        float sg = sigf(plw[i + 1]);
        float wsg = sigf(outw[i + 1]);
        float csc = ci * sc;
        float* vp = g_vn + ((((size_t)i * BB + b) * COUT + co) << 10);
        float ss = 0.f;
        #pragma unroll
        for (int p = 0; p < 8; p++) {
            float y = acc[i][p] * csc + sh;
            float vold = vp[pxbase + p];
            float v = vold + (y - vold) * sg;
            float sp = (v >= 1.f) ? 1.f : 0.f;
            vp[pxbase + p] = (v >= 1.f) ? 0.f : v;
            outacc[p] += wsg * sp;
            ss += sp;
        }
        spsum[i] = ss;
    }
    float* dop = dout + ((((size_t)t * BB + b) * COUT + co)) * 1024;
    #pragma unroll
    for (int p = 0; p < 8; p++) dop[pxbase + p] += outacc[p];

    // Per-node spike mean (per half-block = per c_out)
    float* red = in_s;
    for (int i = 0; i < 5; i++) {
        __syncthreads();
        red[tid] = spsum[i];
        __syncthreads();
        for (int off = 64; off; off >>= 1) {
            if (t2 < off) red[tid] += red[tid + off];
            __syncthreads();
        }
        if (t2 == 0) g_msp[((size_t)i * BB + b) * COUT + co] = red[half * 128] * (1.f / 1024.f);
    }
}

// ---------------------------------------------------------------------------
// K5: feats_i = relu(spike_mean @ ft_w^T + ft_b); end-of-step trace update
// grid (B), 128 threads
// ---------------------------------------------------------------------------
__global__ void k5_feats(const float* __restrict__ ftw, const float* __restrict__ ftb) {
    int b = blockIdx.x, tid = threadIdx.x;
    __shared__ float ms[5 * COUT];
    for (int i = 0; i < 5; i++) ms[i * COUT + tid] = g_msp[((size_t)i * BB + b) * COUT + tid];
    __syncthreads();
    float feats[6];
    feats[0] = g_feat0[b * COUT + tid];
    for (int i = 0; i < 5; i++) {
        float f = ftb[tid];
        for (int d = 0; d < COUT; d++) f += ms[i * COUT + d] * ftw[tid * COUT + d];
        feats[i + 1] = fmaxf(f, 0.f);
    }
    for (int n = 0; n < NN; n++) {
        size_t ix = ((size_t)b * NN + n) * COUT + tid;
        g_traces[ix] = 0.6f * g_traces[ix] + 0.4f * feats[n];
    }
}

// ---------------------------------------------------------------------------
extern "C" void kernel_launch(void* const* d_in, const int* in_sizes, int n_in,
                              void* d_out, int out_size) {
    const float* x       = (const float*)d_in[0];
    const float* conv0_w = (const float*)d_in[1];
    const float* bn0_g   = (const float*)d_in[2];
    const float* bn0_b   = (const float*)d_in[3];
    const float* bn0_m   = (const float*)d_in[4];
    const float* bn0_v   = (const float*)d_in[5];
    const float* convs_w = (const float*)d_in[6];
    const float* bns_g   = (const float*)d_in[7];
    const float* bns_b   = (const float*)d_in[8];
    const float* bns_m   = (const float*)d_in[9];
    const float* bns_v   = (const float*)d_in[10];
    const float* plif_w  = (const float*)d_in[11];
    const float* ft_w    = (const float*)d_in[12];
    const float* ft_b    = (const float*)d_in[13];
    const float* gat_W   = (const float*)d_in[14];
    const float* gat_a   = (const float*)d_in[15];
    const float* out_w   = (const float*)d_in[16];
    float* dout = (float*)d_out;

    const int k1_smem = 3 * 66 * 66 * (int)sizeof(float);  // 52272 B
    cudaFuncSetAttribute(k1_conv0, cudaFuncAttributeMaxDynamicSharedMemorySize, k1_smem);

    k0_zero<<<2048, 256>>>();
    for (int t = 0; t < TT; t++) {
        k1_conv0<<<dim3(BB, COUT), 256, k1_smem>>>(x, conv0_w, bn0_g, bn0_b, bn0_m, bn0_v,
                                                   plif_w, out_w, dout, t);
        k2_graph<<<BB, 128>>>(ft_w, ft_b, gat_W, gat_a);
        k3_nodeconv<<<dim3(BB, COUT / 2), 256>>>(convs_w, bns_g, bns_b, bns_m, bns_v,
                                                 plif_w, out_w, dout, t);
        k5_feats<<<BB, 128>>>(ft_w, ft_b);
    }
}